// round 10
// baseline (speedup 1.0000x reference)
#include <cuda_runtime.h>
#include <cuda_fp16.h>
#include <math.h>
#include <stdint.h>

#define HDIM 512
#define BATCH 8
#define SEQL 1024
#define MTOT 8192

// half scratch: 84M halves = 168MB
__device__ __half g_scratch[(size_t)84 * 1024 * 1024];

// ---------------------------------------------------------------------------
// Primitives
// ---------------------------------------------------------------------------
__device__ __forceinline__ void mma_f16(float& d0, float& d1, float& d2, float& d3,
                                        uint32_t a0, uint32_t a1, uint32_t a2, uint32_t a3,
                                        uint32_t b0, uint32_t b1)
{
    asm volatile(
        "mma.sync.aligned.m16n8k16.row.col.f32.f16.f16.f32 "
        "{%0,%1,%2,%3}, {%4,%5,%6,%7}, {%8,%9}, {%0,%1,%2,%3};"
        : "+f"(d0), "+f"(d1), "+f"(d2), "+f"(d3)
        : "r"(a0), "r"(a1), "r"(a2), "r"(a3), "r"(b0), "r"(b1));
}

__device__ __forceinline__ void ldsm4(uint32_t& r0, uint32_t& r1, uint32_t& r2, uint32_t& r3,
                                      uint32_t addr)
{
    asm volatile("ldmatrix.sync.aligned.m8n8.x4.shared.b16 {%0,%1,%2,%3}, [%4];"
                 : "=r"(r0), "=r"(r1), "=r"(r2), "=r"(r3) : "r"(addr));
}
__device__ __forceinline__ void ldsm4t(uint32_t& r0, uint32_t& r1, uint32_t& r2, uint32_t& r3,
                                       uint32_t addr)
{
    asm volatile("ldmatrix.sync.aligned.m8n8.x4.trans.shared.b16 {%0,%1,%2,%3}, [%4];"
                 : "=r"(r0), "=r"(r1), "=r"(r2), "=r"(r3) : "r"(addr));
}

__device__ __forceinline__ void cp16(uint32_t dst, const void* src) {
    asm volatile("cp.async.cg.shared.global [%0], [%1], 16;" :: "r"(dst), "l"(src));
}
__device__ __forceinline__ void cpcommit() { asm volatile("cp.async.commit_group;"); }
template<int N> __device__ __forceinline__ void cpwait() {
    asm volatile("cp.async.wait_group %0;" :: "n"(N));
}

// XOR swizzle: rows of 128B (64 halves), 16B chunk c in 0..7
__device__ __forceinline__ uint32_t swz(uint32_t r, uint32_t c) {
    return r * 128u + ((c ^ (r & 7u)) << 4);
}

__device__ __forceinline__ uint32_t packh2(float x, float y) {
    __half2 h = __floats2half2_rn(x, y);
    return *(uint32_t*)&h;
}

// ---------------------------------------------------------------------------
// fp32 -> fp16 conversion kernel (weights only now)
// ---------------------------------------------------------------------------
struct CvtP { const float* src[11]; __half* dst[11]; int nblk[11]; };

__global__ __launch_bounds__(256) void cvt_k(CvtP P)
{
    int b = blockIdx.x;
    int s = 0;
    while (b >= P.nblk[s]) { b -= P.nblk[s]; ++s; }
    size_t i = ((size_t)b * 256 + threadIdx.x) * 4;
    float4 v = *(const float4*)(P.src[s] + i);
    uint2 o;
    o.x = packh2(v.x, v.y);
    o.y = packh2(v.z, v.w);
    *(uint2*)(P.dst[s] + i) = o;
}

// ---------------------------------------------------------------------------
// FP16 GEMM (NT): C = A' @ W^T + bias, times per-seg osc, where
//   MODE 0: A' = A1 (half, cp.async)
//   MODE 1: A' = 0.5*(A1+A2) (half, register-staged)
//   MODE 2: A' = cvt_fp16(A32) (fp32 input, converted during staging)
// CTA tile 128x128, BK=64, 256 thr (8 warps 2x4, warp tile 64x32).
// 3-stage cp.async pipeline (96KB smem), single sync/iter, XOR swizzle.
// Up to 6 per-512-col segments.
// ---------------------------------------------------------------------------
struct GemmP {
    const __half* A1[6]; const __half* A2[6]; const float* A32[6];
    const __half* W[6];  const float*  Bi[6];
    __half* Ch[6]; float* Cf;
    float osc[6];
    int lda, ldc, K;
};

template<int MODE, bool OUTF32>
__global__ __launch_bounds__(256, 2) void gemm_k(GemmP P)
{
    extern __shared__ char sm[];
    const uint32_t smb = (uint32_t)__cvta_generic_to_shared(sm);

    const int bm  = blockIdx.y * 128;
    const int bnG = blockIdx.x * 128;
    const int seg = bnG >> 9;
    const int bn  = bnG & 511;
    const __half* A1 = P.A1[seg];
    const __half* A2 = P.A2[seg];
    const float* A32 = P.A32[seg];
    const __half* W  = P.W[seg];
    const float*  BI = P.Bi[seg];
    const float  osc = P.osc[seg];

    const int tid  = threadIdx.x;
    const int warp = tid >> 5;
    const int lane = tid & 31;
    const int g = lane >> 2;
    const int t = lane & 3;
    const int wm = warp >> 2;
    const int wn = warp & 3;
    const int lr = lane & 15;
    const int lh = lane >> 4;

    const int sr = tid >> 1;
    const int sc = (tid & 1) * 4;

    const uint32_t lrow128 = (uint32_t)lr * 128u;
    uint32_t x4[4];
    #pragma unroll
    for (int kb = 0; kb < 4; kb++)
        x4[kb] = (uint32_t)(((kb * 2 + lh) ^ (lr & 7)) << 4);

    const int NK = P.K >> 6;
    float acc[4][4][4] = {};

    auto issueW = [&](int i) {
        const uint32_t dst = smb + (uint32_t)(i % 3) * 32768u + 16384u;
        const __half* src = W + (size_t)(bn + sr) * P.K + i * 64 + sc * 8;
        #pragma unroll
        for (int c = 0; c < 4; c++)
            cp16(dst + swz(sr, sc + c), src + c * 8);
    };
    auto issueA = [&](int i) {
        const uint32_t dst = smb + (uint32_t)(i % 3) * 32768u;
        const __half* src = A1 + (size_t)(bm + sr) * P.lda + i * 64 + sc * 8;
        #pragma unroll
        for (int c = 0; c < 4; c++)
            cp16(dst + swz(sr, sc + c), src + c * 8);
    };
    auto stageA_f = [&](int i) {   // MODE 1: (A1+A2)*0.5, STS half
        char* dstb = sm + (size_t)(i % 3) * 32768u;
        const __half* p1 = A1 + (size_t)(bm + sr) * P.lda + i * 64 + sc * 8;
        const __half* p2 = A2 + (size_t)(bm + sr) * P.lda + i * 64 + sc * 8;
        const __half2 hf = __float2half2_rn(0.5f);
        #pragma unroll
        for (int c = 0; c < 4; c++) {
            float4 x = *(const float4*)(p1 + c * 8);
            float4 y = *(const float4*)(p2 + c * 8);
            const __half2* xh = (const __half2*)&x;
            const __half2* yh = (const __half2*)&y;
            __half2 z[4];
            #pragma unroll
            for (int j = 0; j < 4; j++)
                z[j] = __hmul2(__hadd2(xh[j], yh[j]), hf);
            *(float4*)(dstb + swz(sr, sc + c)) = *(float4*)z;
        }
    };
    auto stageA_c = [&](int i) {   // MODE 2: fp32 -> fp16 during staging
        char* dstb = sm + (size_t)(i % 3) * 32768u;
        const float* p = A32 + (size_t)(bm + sr) * P.lda + i * 64 + sc * 8;
        #pragma unroll
        for (int c = 0; c < 4; c++) {
            float4 x = *(const float4*)(p + c * 8);
            float4 y = *(const float4*)(p + c * 8 + 4);
            uint32_t z[4];
            z[0] = packh2(x.x, x.y);
            z[1] = packh2(x.z, x.w);
            z[2] = packh2(y.x, y.y);
            z[3] = packh2(y.z, y.w);
            *(float4*)(dstb + swz(sr, sc + c)) = *(float4*)z;
        }
    };
    auto stage = [&](int i) {
        if (MODE == 1)      { stageA_f(i); issueW(i); }
        else if (MODE == 2) { stageA_c(i); issueW(i); }
        else                { issueA(i);   issueW(i); }
        cpcommit();
    };

    stage(0);
    if (NK > 1) stage(1);

    for (int i = 0; i < NK; i++) {
        if (i + 1 < NK) cpwait<1>(); else cpwait<0>();
        __syncthreads();

        const uint32_t Ab = smb + (uint32_t)(i % 3) * 32768u;
        const uint32_t Wb = Ab + 16384u;

        #pragma unroll
        for (int kb = 0; kb < 4; kb++) {
            uint32_t bw[2][4];
            #pragma unroll
            for (int np = 0; np < 2; np++)
                ldsm4(bw[np][0], bw[np][1], bw[np][2], bw[np][3],
                      Wb + (uint32_t)(wn * 32 + np * 16) * 128u + lrow128 + x4[kb]);
            #pragma unroll
            for (int mt = 0; mt < 4; mt++) {
                uint32_t a0, a1, a2, a3;
                ldsm4(a0, a1, a2, a3,
                      Ab + (uint32_t)(wm * 64 + mt * 16) * 128u + lrow128 + x4[kb]);
                #pragma unroll
                for (int nt = 0; nt < 4; nt++) {
                    const int np = nt >> 1, hi = nt & 1;
                    mma_f16(acc[mt][nt][0], acc[mt][nt][1], acc[mt][nt][2], acc[mt][nt][3],
                            a0, a1, a2, a3,
                            bw[np][hi ? 1 : 0], bw[np][hi ? 3 : 2]);
                }
            }
        }

        if (i + 2 < NK) stage(i + 2);
    }

    #pragma unroll
    for (int mt = 0; mt < 4; mt++) {
        const int r = bm + wm * 64 + mt * 16 + g;
        #pragma unroll
        for (int nt = 0; nt < 4; nt++) {
            const int cl = bn + wn * 32 + nt * 8 + 2 * t;
            const float bx = BI[cl], by = BI[cl + 1];
            if (OUTF32) {
                float* Cf = P.Cf;
                *(float2*)(Cf + (size_t)r * P.ldc + cl) =
                    make_float2((acc[mt][nt][0] + bx) * osc, (acc[mt][nt][1] + by) * osc);
                *(float2*)(Cf + (size_t)(r + 8) * P.ldc + cl) =
                    make_float2((acc[mt][nt][2] + bx) * osc, (acc[mt][nt][3] + by) * osc);
            } else {
                __half* Ch = P.Ch[seg];
                *(uint32_t*)(Ch + (size_t)r * P.ldc + cl) =
                    packh2((acc[mt][nt][0] + bx) * osc, (acc[mt][nt][1] + by) * osc);
                *(uint32_t*)(Ch + (size_t)(r + 8) * P.ldc + cl) =
                    packh2((acc[mt][nt][2] + bx) * osc, (acc[mt][nt][3] + by) * osc);
            }
        }
    }
}

// ---------------------------------------------------------------------------
// FP16 flash attention (R8 winner — unchanged).
// Softmax: exp2 in packed fp16; li via ones-matrix MMA.
// Q pre-scaled by (1/8)*log2(e) upstream -> S is log2-domain.
// 3-stage cp.async K/V ring, 1 sync/tile. Grid: (L/128, NH, z=(combo,batch)).
// ---------------------------------------------------------------------------
struct FlashP {
    const __half *Qp[4], *Kp[4], *Vp[4]; __half* Op[4];
    int sq, skv, so, cmask, cshift;
};

__global__ __launch_bounds__(256, 2) void flash_k(FlashP P)
{
    extern __shared__ char fsm[];
    const uint32_t smb = (uint32_t)__cvta_generic_to_shared(fsm);
    // Q @0 (16KB), K[s] @16384+s*8192 (3), V[s] @40960+s*8192 (3) = 64KB

    const int z = blockIdx.z;
    const int c = z & P.cmask;
    const int b = z >> P.cshift;
    const int q0 = blockIdx.x * 128;
    const int h  = blockIdx.y;

    const int tid = threadIdx.x;
    const int w = tid >> 5;
    const int lane = tid & 31;
    const int g = lane >> 2;
    const int t = lane & 3;
    const int lr = lane & 15;
    const int lh = lane >> 4;

    const __half* Qb = P.Qp[c] + (size_t)b * SEQL * P.sq  + (size_t)h * 64;
    const __half* Kb = P.Kp[c] + (size_t)b * SEQL * P.skv + (size_t)h * 64;
    const __half* Vb = P.Vp[c] + (size_t)b * SEQL * P.skv + (size_t)h * 64;
    __half*       Ob = P.Op[c] + (size_t)b * SEQL * P.so  + (size_t)h * 64;

    const uint32_t lrow128 = (uint32_t)lr * 128u;
    uint32_t x4[4];
    #pragma unroll
    for (int kb = 0; kb < 4; kb++)
        x4[kb] = (uint32_t)(((kb * 2 + lh) ^ (lr & 7)) << 4);

    {
        const int sr = tid >> 1;
        const int sc = (tid & 1) * 4;
        const __half* src = Qb + (size_t)(q0 + sr) * P.sq + sc * 8;
        #pragma unroll
        for (int cc = 0; cc < 4; cc++)
            cp16(smb + swz(sr, sc + cc), src + cc * 8);
        cpcommit();
    }

    const int kr = tid >> 2;
    const int kc = (tid & 3) * 2;
    auto stageKV = [&](int kt, int s) {
        const __half* pk = Kb + (size_t)(kt + kr) * P.skv + kc * 8;
        const __half* pv = Vb + (size_t)(kt + kr) * P.skv + kc * 8;
        const uint32_t kbase = smb + 16384u + (uint32_t)s * 8192u;
        const uint32_t vbase = smb + 40960u + (uint32_t)s * 8192u;
        cp16(kbase + swz(kr, kc),     pk);
        cp16(kbase + swz(kr, kc + 1), pk + 8);
        cp16(vbase + swz(kr, kc),     pv);
        cp16(vbase + swz(kr, kc + 1), pv + 8);
        cpcommit();
    };

    stageKV(0, 0);
    stageKV(64, 1);
    cpwait<1>();
    __syncthreads();

    uint32_t qa[4][4];
    #pragma unroll
    for (int kb = 0; kb < 4; kb++)
        ldsm4(qa[kb][0], qa[kb][1], qa[kb][2], qa[kb][3],
              smb + (uint32_t)(w * 2048) + lrow128 + x4[kb]);

    float oacc[8][4] = {};
    float mi0 = -INFINITY, mi1 = -INFINITY;
    float li0 = 0.f, li1 = 0.f;

    const uint32_t ONES = 0x3C003C00u;

    const int NT = SEQL / 64;
    for (int it = 0; it < NT; it++) {
        const int s = it % 3;
        const uint32_t Kbase = smb + 16384u + (uint32_t)s * 8192u + lrow128;
        const uint32_t Vbase = smb + 40960u + (uint32_t)s * 8192u + lrow128;

        float sacc[8][4] = {};
        #pragma unroll
        for (int kb = 0; kb < 4; kb++) {
            #pragma unroll
            for (int np = 0; np < 4; np++) {
                uint32_t k0, k1, k2, k3;
                ldsm4(k0, k1, k2, k3, Kbase + (uint32_t)(np * 2048) + x4[kb]);
                mma_f16(sacc[2*np][0], sacc[2*np][1], sacc[2*np][2], sacc[2*np][3],
                        qa[kb][0], qa[kb][1], qa[kb][2], qa[kb][3], k0, k2);
                mma_f16(sacc[2*np+1][0], sacc[2*np+1][1], sacc[2*np+1][2], sacc[2*np+1][3],
                        qa[kb][0], qa[kb][1], qa[kb][2], qa[kb][3], k1, k3);
            }
        }

        uint32_t pa[4][4];
        {
            float mx0 = -INFINITY, mx1 = -INFINITY;
            #pragma unroll
            for (int nt = 0; nt < 8; nt++) {
                mx0 = fmaxf(mx0, fmaxf(sacc[nt][0], sacc[nt][1]));
                mx1 = fmaxf(mx1, fmaxf(sacc[nt][2], sacc[nt][3]));
            }
            mx0 = fmaxf(mx0, __shfl_xor_sync(0xffffffffu, mx0, 1, 4));
            mx0 = fmaxf(mx0, __shfl_xor_sync(0xffffffffu, mx0, 2, 4));
            mx1 = fmaxf(mx1, __shfl_xor_sync(0xffffffffu, mx1, 1, 4));
            mx1 = fmaxf(mx1, __shfl_xor_sync(0xffffffffu, mx1, 2, 4));
            const float mn0 = fmaxf(mi0, mx0);
            const float mn1 = fmaxf(mi1, mx1);
            const float c0 = exp2f(mi0 - mn0);
            const float c1 = exp2f(mi1 - mn1);
            mi0 = mn0; mi1 = mn1;

            float ls[4] = {0.f, 0.f, 0.f, 0.f};
            #pragma unroll
            for (int kb = 0; kb < 4; kb++) {
                __half2 e0 = h2exp2(__floats2half2_rn(sacc[2*kb][0]   - mn0, sacc[2*kb][1]   - mn0));
                __half2 e1 = h2exp2(__floats2half2_rn(sacc[2*kb][2]   - mn1, sacc[2*kb][3]   - mn1));
                __half2 e2 = h2exp2(__floats2half2_rn(sacc[2*kb+1][0] - mn0, sacc[2*kb+1][1] - mn0));
                __half2 e3 = h2exp2(__floats2half2_rn(sacc[2*kb+1][2] - mn1, sacc[2*kb+1][3] - mn1));
                pa[kb][0] = *(uint32_t*)&e0;
                pa[kb][1] = *(uint32_t*)&e1;
                pa[kb][2] = *(uint32_t*)&e2;
                pa[kb][3] = *(uint32_t*)&e3;
                mma_f16(ls[0], ls[1], ls[2], ls[3],
                        pa[kb][0], pa[kb][1], pa[kb][2], pa[kb][3], ONES, ONES);
            }
            li0 = li0 * c0 + ls[0];
            li1 = li1 * c1 + ls[2];

            const bool skip = __all_sync(0xffffffffu, (c0 == 1.0f) & (c1 == 1.0f));
            if (!skip) {
                #pragma unroll
                for (int nt = 0; nt < 8; nt++) {
                    oacc[nt][0] *= c0; oacc[nt][1] *= c0;
                    oacc[nt][2] *= c1; oacc[nt][3] *= c1;
                }
            }
        }

        #pragma unroll
        for (int kb = 0; kb < 4; kb++) {
            #pragma unroll
            for (int np = 0; np < 4; np++) {
                uint32_t v0, v1, v2, v3;
                ldsm4t(v0, v1, v2, v3, Vbase + (uint32_t)(kb * 2048) + x4[np]);
                mma_f16(oacc[2*np][0], oacc[2*np][1], oacc[2*np][2], oacc[2*np][3],
                        pa[kb][0], pa[kb][1], pa[kb][2], pa[kb][3], v0, v1);
                mma_f16(oacc[2*np+1][0], oacc[2*np+1][1], oacc[2*np+1][2], oacc[2*np+1][3],
                        pa[kb][0], pa[kb][1], pa[kb][2], pa[kb][3], v2, v3);
            }
        }

        if (it + 1 < NT) {
            if (it + 2 < NT) { stageKV((it + 2) * 64, (it + 2) % 3); cpwait<1>(); }
            else             { cpwait<0>(); }
            __syncthreads();
        }
    }

    {
        const float inv0 = 1.0f / li0;
        const float inv1 = 1.0f / li1;
        const int r0 = q0 + 16 * w + g;
        #pragma unroll
        for (int nt = 0; nt < 8; nt++) {
            const int col = nt * 8 + 2 * t;
            *(uint32_t*)(Ob + (size_t)r0 * P.so + col) =
                packh2(oacc[nt][0] * inv0, oacc[nt][1] * inv0);
            *(uint32_t*)(Ob + (size_t)(r0 + 8) * P.so + col) =
                packh2(oacc[nt][2] * inv1, oacc[nt][3] * inv1);
        }
    }
}

// ---------------------------------------------------------------------------
extern "C" void kernel_launch(void* const* d_in, const int* in_sizes, int n_in,
                              void* d_out, int out_size)
{
    (void)in_sizes; (void)n_in; (void)out_size;

    const float* hs        = (const float*)d_in[0];
    const float* txt       = (const float*)d_in[1];
    const float* w_q_img   = (const float*)d_in[2];
    const float* b_q_img   = (const float*)d_in[3];
    const float* w_k_img   = (const float*)d_in[4];
    const float* b_k_img   = (const float*)d_in[5];
    const float* w_v_img   = (const float*)d_in[6];
    const float* b_v_img   = (const float*)d_in[7];
    const float* w_q_txt   = (const float*)d_in[8];
    const float* b_q_txt   = (const float*)d_in[9];
    const float* w_k_txt   = (const float*)d_in[10];
    const float* b_k_txt   = (const float*)d_in[11];
    const float* w_v_txt   = (const float*)d_in[12];
    const float* b_v_txt   = (const float*)d_in[13];
    const float* w_out_img = (const float*)d_in[14];
    const float* b_out_img = (const float*)d_in[15];
    const float* w_out_txt = (const float*)d_in[16];
    const float* b_out_txt = (const float*)d_in[17];
    const float* w_cat     = (const float*)d_in[18];
    const float* b_cat     = (const float*)d_in[19];
    const float* in_proj_w = (const float*)d_in[20];
    const float* in_proj_b = (const float*)d_in[21];
    const float* out_proj_w= (const float*)d_in[22];
    const float* out_proj_b= (const float*)d_in[23];
    float* out = (float*)d_out;

    constexpr size_t U  = (size_t)MTOT * HDIM;
    constexpr size_t QW = (size_t)512 * 512;
    const float qsc = 0.125f * 1.4426950408889634f;  // (1/sqrt(64))*log2(e)

    __half* S;
    cudaGetSymbolAddress((void**)&S, g_scratch);

    __half* QKV0h  = S + 2 * U;
    __half* QKV1h  = S + 5 * U;
    __half* C0     = S + 8 * U;
    __half* C1     = S + 9 * U;
    __half* C2     = S + 10 * U;
    __half* C3     = S + 11 * U;
    __half* OUTCATh= S + 12 * U;
    __half* OUTBh  = S + 14 * U;
    __half* QKV2h  = S + 15 * U;
    __half* CTXh   = S + 18 * U;
    __half* WB     = S + 19 * U;
    __half* whqi = WB;           __half* whki = WB + QW;     __half* whvi = WB + 2 * QW;
    __half* whqt = WB + 3 * QW;  __half* whkt = WB + 4 * QW; __half* whvt = WB + 5 * QW;
    __half* whoi = WB + 6 * QW;  __half* whot = WB + 7 * QW; __half* whop = WB + 8 * QW;
    __half* whcat = WB + 9 * QW;            // 512*1024
    __half* whinp = whcat + 512 * 1024;     // 1536*512

    const int GSM = 98304, FSM = 65536;
    cudaFuncSetAttribute(gemm_k<0,false>, cudaFuncAttributeMaxDynamicSharedMemorySize, GSM);
    cudaFuncSetAttribute(gemm_k<1,false>, cudaFuncAttributeMaxDynamicSharedMemorySize, GSM);
    cudaFuncSetAttribute(gemm_k<2,false>, cudaFuncAttributeMaxDynamicSharedMemorySize, GSM);
    cudaFuncSetAttribute(gemm_k<0,true>,  cudaFuncAttributeMaxDynamicSharedMemorySize, GSM);
    cudaFuncSetAttribute(flash_k,         cudaFuncAttributeMaxDynamicSharedMemorySize, FSM);

    // 0) fp32 -> fp16 conversions (weights only — inputs fused into QKV gemm)
    {
        CvtP p;
        const float* srcs[11] = {w_q_img, w_k_img, w_v_img, w_q_txt, w_k_txt,
                                 w_v_txt, w_out_img, w_out_txt, out_proj_w, w_cat, in_proj_w};
        __half* dsts[11] = {whqi, whki, whvi, whqt, whkt,
                            whvt, whoi, whot, whop, whcat, whinp};
        int ns[11] = {(int)QW, (int)QW, (int)QW, (int)QW, (int)QW,
                      (int)QW, (int)QW, (int)QW, (int)QW, 512*1024, 1536*512};
        int tot = 0;
        for (int i = 0; i < 11; i++) { p.src[i]=srcs[i]; p.dst[i]=dsts[i]; p.nblk[i]=ns[i]/1024; tot+=ns[i]/1024; }
        cvt_k<<<tot, 256>>>(p);
    }

    const dim3 blk(256);

    // 1) BOTH QKV projections in one launch (6 segments), fp32 A converted
    //    in-staging; Q columns pre-scaled by qsc.
    {
        GemmP p = {};
        p.A32[0] = p.A32[1] = p.A32[2] = hs;
        p.A32[3] = p.A32[4] = p.A32[5] = txt;
        p.W[0] = whqi; p.W[1] = whki; p.W[2] = whvi;
        p.W[3] = whqt; p.W[4] = whkt; p.W[5] = whvt;
        p.Bi[0] = b_q_img; p.Bi[1] = b_k_img; p.Bi[2] = b_v_img;
        p.Bi[3] = b_q_txt; p.Bi[4] = b_k_txt; p.Bi[5] = b_v_txt;
        p.Ch[0] = QKV0h; p.Ch[1] = QKV0h + 512; p.Ch[2] = QKV0h + 1024;
        p.Ch[3] = QKV1h; p.Ch[4] = QKV1h + 512; p.Ch[5] = QKV1h + 1024;
        p.osc[0] = qsc; p.osc[1] = 1.f; p.osc[2] = 1.f;
        p.osc[3] = qsc; p.osc[4] = 1.f; p.osc[5] = 1.f;
        p.lda = HDIM; p.ldc = 3 * HDIM; p.K = HDIM;
        gemm_k<2,false><<<dim3(24, 64), blk, GSM>>>(p);
    }

    // 2) four attentions in one launch
    {
        FlashP p;
        p.Qp[0] = QKV0h; p.Kp[0] = QKV0h + 512; p.Vp[0] = QKV0h + 1024; p.Op[0] = C0;
        p.Qp[1] = QKV1h; p.Kp[1] = QKV1h + 512; p.Vp[1] = QKV1h + 1024; p.Op[1] = C1;
        p.Qp[2] = QKV0h; p.Kp[2] = QKV1h + 512; p.Vp[2] = QKV1h + 1024; p.Op[2] = C2;
        p.Qp[3] = QKV1h; p.Kp[3] = QKV0h + 512; p.Vp[3] = QKV0h + 1024; p.Op[3] = C3;
        p.sq = 3 * HDIM; p.skv = 3 * HDIM; p.so = HDIM; p.cmask = 3; p.cshift = 2;
        flash_k<<<dim3(SEQL / 128, 8, BATCH * 4), blk, FSM>>>(p);
    }

    // 3) merged out_img / out_txt: (a+b)*0.5 -> concat halves
    {
        GemmP p = {};
        p.A1[0] = C0; p.A2[0] = C2; p.A1[1] = C1; p.A2[1] = C3;
        p.W[0] = whoi; p.W[1] = whot;
        p.Bi[0] = b_out_img; p.Bi[1] = b_out_txt;
        p.Ch[0] = OUTCATh; p.Ch[1] = OUTCATh + 512;
        p.osc[0] = p.osc[1] = 1.f;
        p.lda = HDIM; p.ldc = 2 * HDIM; p.K = HDIM;
        gemm_k<1,false><<<dim3(8, 64), blk, GSM>>>(p);
    }

    // 4) cat linear (K=1024)
    {
        GemmP p = {};
        p.A1[0] = OUTCATh; p.W[0] = whcat; p.Bi[0] = b_cat;
        p.Ch[0] = OUTBh; p.osc[0] = 1.f;
        p.lda = 2 * HDIM; p.ldc = HDIM; p.K = 2 * HDIM;
        gemm_k<0,false><<<dim3(4, 64), blk, GSM>>>(p);
    }

    // 5) pooling in_proj, Q pre-scaled
    {
        GemmP p = {};
        p.A1[0] = p.A1[1] = p.A1[2] = OUTBh;
        p.W[0] = whinp; p.W[1] = whinp + 512 * 512; p.W[2] = whinp + 1024 * 512;
        p.Bi[0] = in_proj_b; p.Bi[1] = in_proj_b + 512; p.Bi[2] = in_proj_b + 1024;
        p.Ch[0] = QKV2h; p.Ch[1] = QKV2h + 512; p.Ch[2] = QKV2h + 1024;
        p.osc[0] = qsc; p.osc[1] = 1.f; p.osc[2] = 1.f;
        p.lda = HDIM; p.ldc = 3 * HDIM; p.K = HDIM;
        gemm_k<0,false><<<dim3(12, 64), blk, GSM>>>(p);
    }

    // 6) pooling self-attention
    {
        FlashP p;
        p.Qp[0] = QKV2h; p.Kp[0] = QKV2h + 512; p.Vp[0] = QKV2h + 1024; p.Op[0] = CTXh;
        p.Qp[1] = p.Qp[2] = p.Qp[3] = QKV2h;
        p.Kp[1] = p.Kp[2] = p.Kp[3] = QKV2h + 512;
        p.Vp[1] = p.Vp[2] = p.Vp[3] = QKV2h + 1024;
        p.Op[1] = p.Op[2] = p.Op[3] = CTXh;
        p.sq = 3 * HDIM; p.skv = 3 * HDIM; p.so = HDIM; p.cmask = 0; p.cshift = 0;
        flash_k<<<dim3(SEQL / 128, 8, BATCH), blk, FSM>>>(p);
    }

    // 7) out_proj -> fp32 output
    {
        GemmP p = {};
        p.A1[0] = CTXh; p.W[0] = whop; p.Bi[0] = out_proj_b;
        p.Cf = out; p.osc[0] = 1.f;
        p.lda = HDIM; p.ldc = HDIM; p.K = HDIM;
        gemm_k<0,true><<<dim3(4, 64), blk, GSM>>>(p);
    }
}

// round 11
// speedup vs baseline: 1.1099x; 1.1099x over previous
#include <cuda_runtime.h>
#include <cuda_fp16.h>
#include <math.h>
#include <stdint.h>

#define HDIM 512
#define BATCH 8
#define SEQL 1024
#define MTOT 8192

// half scratch: 84M halves = 168MB
__device__ __half g_scratch[(size_t)84 * 1024 * 1024];
__device__ float zbias[512] = {};   // zero bias for prep gemm

// ---------------------------------------------------------------------------
// Primitives
// ---------------------------------------------------------------------------
__device__ __forceinline__ void mma_f16(float& d0, float& d1, float& d2, float& d3,
                                        uint32_t a0, uint32_t a1, uint32_t a2, uint32_t a3,
                                        uint32_t b0, uint32_t b1)
{
    asm volatile(
        "mma.sync.aligned.m16n8k16.row.col.f32.f16.f16.f32 "
        "{%0,%1,%2,%3}, {%4,%5,%6,%7}, {%8,%9}, {%0,%1,%2,%3};"
        : "+f"(d0), "+f"(d1), "+f"(d2), "+f"(d3)
        : "r"(a0), "r"(a1), "r"(a2), "r"(a3), "r"(b0), "r"(b1));
}

__device__ __forceinline__ void ldsm4(uint32_t& r0, uint32_t& r1, uint32_t& r2, uint32_t& r3,
                                      uint32_t addr)
{
    asm volatile("ldmatrix.sync.aligned.m8n8.x4.shared.b16 {%0,%1,%2,%3}, [%4];"
                 : "=r"(r0), "=r"(r1), "=r"(r2), "=r"(r3) : "r"(addr));
}
__device__ __forceinline__ void ldsm4t(uint32_t& r0, uint32_t& r1, uint32_t& r2, uint32_t& r3,
                                       uint32_t addr)
{
    asm volatile("ldmatrix.sync.aligned.m8n8.x4.trans.shared.b16 {%0,%1,%2,%3}, [%4];"
                 : "=r"(r0), "=r"(r1), "=r"(r2), "=r"(r3) : "r"(addr));
}

__device__ __forceinline__ void cp16(uint32_t dst, const void* src) {
    asm volatile("cp.async.cg.shared.global [%0], [%1], 16;" :: "r"(dst), "l"(src));
}
__device__ __forceinline__ void cpcommit() { asm volatile("cp.async.commit_group;"); }
template<int N> __device__ __forceinline__ void cpwait() {
    asm volatile("cp.async.wait_group %0;" :: "n"(N));
}

// XOR swizzle: rows of 128B (64 halves), 16B chunk c in 0..7
__device__ __forceinline__ uint32_t swz(uint32_t r, uint32_t c) {
    return r * 128u + ((c ^ (r & 7u)) << 4);
}

__device__ __forceinline__ uint32_t packh2(float x, float y) {
    __half2 h = __floats2half2_rn(x, y);
    return *(uint32_t*)&h;
}

// ---------------------------------------------------------------------------
// fp32 -> fp16 conversion kernel
// ---------------------------------------------------------------------------
struct CvtP { const float* src[13]; __half* dst[13]; int nblk[13]; };

__global__ __launch_bounds__(256) void cvt_k(CvtP P)
{
    int b = blockIdx.x;
    int s = 0;
    while (b >= P.nblk[s]) { b -= P.nblk[s]; ++s; }
    size_t i = ((size_t)b * 256 + threadIdx.x) * 4;
    float4 v = *(const float4*)(P.src[s] + i);
    uint2 o;
    o.x = packh2(v.x, v.y);
    o.y = packh2(v.z, v.w);
    *(uint2*)(P.dst[s] + i) = o;
}

// ---------------------------------------------------------------------------
// transpose + cvt: dst[n,k] = fp16(src[k,n]) for 512x512 fp32 matrices
// grid (16,16,2), block (32,8)
// ---------------------------------------------------------------------------
struct TrP { const float* src[2]; __half* dst[2]; };

__global__ void tcv_k(TrP P)
{
    __shared__ __half tile[32][33];
    const int s = blockIdx.z;
    const int x = blockIdx.x * 32, y = blockIdx.y * 32;
    const int tx = threadIdx.x, ty = threadIdx.y;
    const float* src = P.src[s];
    #pragma unroll
    for (int r = ty; r < 32; r += 8)
        tile[r][tx] = __float2half_rn(src[(size_t)(y + r) * 512 + x + tx]);
    __syncthreads();
    __half* dst = P.dst[s];
    #pragma unroll
    for (int r = ty; r < 32; r += 8)
        dst[(size_t)(x + r) * 512 + y + tx] = tile[tx][r];
}

// ---------------------------------------------------------------------------
// bias combine: bout[n] = bcat[n] + sum_j wcat[n,j]*([boi;bot])[j]
// grid 512, block 256
// ---------------------------------------------------------------------------
__global__ void biascomb_k(const float* __restrict__ wcat,
                           const float* __restrict__ boi,
                           const float* __restrict__ bot,
                           const float* __restrict__ bcat,
                           float* __restrict__ bout)
{
    __shared__ float red[256];
    const int n = blockIdx.x;
    float s = 0.f;
    for (int j = threadIdx.x; j < 1024; j += 256) {
        const float b = (j < 512) ? boi[j] : bot[j - 512];
        s += wcat[(size_t)n * 1024 + j] * b;
    }
    red[threadIdx.x] = s;
    __syncthreads();
    #pragma unroll
    for (int o = 128; o; o >>= 1) {
        if (threadIdx.x < o) red[threadIdx.x] += red[threadIdx.x + o];
        __syncthreads();
    }
    if (threadIdx.x == 0) bout[n] = red[0] + bcat[n];
}

// ---------------------------------------------------------------------------
// FP16 GEMM (NT): C = A' @ W^T + bias, times per-seg osc, where
//   MODE 0: A' = A1 (half, cp.async)
//   MODE 1: A' = 0.5*(A1+A2) for k < KA, 0.5*(A1b+A2b) for k >= KA
// CTA tile 128x128, BK=64, 256 thr (8 warps 2x4, warp tile 64x32).
// 3-stage cp.async pipeline (96KB smem), single sync/iter, XOR swizzle.
// ---------------------------------------------------------------------------
struct GemmP {
    const __half* A1[3];  const __half* A2[3];
    const __half* A1b[3]; const __half* A2b[3];
    const __half* W[3];   const float*  Bi[3];
    __half* Ch[3]; float* Cf;
    float osc[3];
    int lda, ldc, K, KA;
};

template<int MODE, bool OUTF32>
__global__ __launch_bounds__(256, 2) void gemm_k(GemmP P)
{
    extern __shared__ char sm[];
    const uint32_t smb = (uint32_t)__cvta_generic_to_shared(sm);

    const int bm  = blockIdx.y * 128;
    const int bnG = blockIdx.x * 128;
    const int seg = bnG >> 9;
    const int bn  = bnG & 511;
    const __half* A1  = P.A1[seg];
    const __half* A2  = P.A2[seg];
    const __half* A1b = P.A1b[seg];
    const __half* A2b = P.A2b[seg];
    const __half* W   = P.W[seg];
    const float*  BI  = P.Bi[seg];
    const float  osc  = P.osc[seg];

    const int tid  = threadIdx.x;
    const int warp = tid >> 5;
    const int lane = tid & 31;
    const int g = lane >> 2;
    const int t = lane & 3;
    const int wm = warp >> 2;
    const int wn = warp & 3;
    const int lr = lane & 15;
    const int lh = lane >> 4;

    const int sr = tid >> 1;
    const int sc = (tid & 1) * 4;

    const uint32_t lrow128 = (uint32_t)lr * 128u;
    uint32_t x4[4];
    #pragma unroll
    for (int kb = 0; kb < 4; kb++)
        x4[kb] = (uint32_t)(((kb * 2 + lh) ^ (lr & 7)) << 4);

    const int NK = P.K >> 6;
    float acc[4][4][4] = {};

    auto issueW = [&](int i) {
        const uint32_t dst = smb + (uint32_t)(i % 3) * 32768u + 16384u;
        const __half* src = W + (size_t)(bn + sr) * P.K + i * 64 + sc * 8;
        #pragma unroll
        for (int c = 0; c < 4; c++)
            cp16(dst + swz(sr, sc + c), src + c * 8);
    };
    auto issueA = [&](int i) {
        const uint32_t dst = smb + (uint32_t)(i % 3) * 32768u;
        const __half* src = A1 + (size_t)(bm + sr) * P.lda + i * 64 + sc * 8;
        #pragma unroll
        for (int c = 0; c < 4; c++)
            cp16(dst + swz(sr, sc + c), src + c * 8);
    };
    auto stageA_f = [&](int i) {   // MODE 1: (pair sum)*0.5, k-split at KA
        int k0 = i * 64;
        const __half* p1b = A1;
        const __half* p2b = A2;
        if (k0 >= P.KA) { p1b = A1b; p2b = A2b; k0 -= P.KA; }
        char* dstb = sm + (size_t)(i % 3) * 32768u;
        const __half* p1 = p1b + (size_t)(bm + sr) * P.lda + k0 + sc * 8;
        const __half* p2 = p2b + (size_t)(bm + sr) * P.lda + k0 + sc * 8;
        const __half2 hf = __float2half2_rn(0.5f);
        #pragma unroll
        for (int c = 0; c < 4; c++) {
            float4 x = *(const float4*)(p1 + c * 8);
            float4 y = *(const float4*)(p2 + c * 8);
            const __half2* xh = (const __half2*)&x;
            const __half2* yh = (const __half2*)&y;
            __half2 z[4];
            #pragma unroll
            for (int j = 0; j < 4; j++)
                z[j] = __hmul2(__hadd2(xh[j], yh[j]), hf);
            *(float4*)(dstb + swz(sr, sc + c)) = *(float4*)z;
        }
    };
    auto stage = [&](int i) {
        if (MODE == 1) { stageA_f(i); issueW(i); }
        else           { issueA(i);   issueW(i); }
        cpcommit();
    };

    stage(0);
    if (NK > 1) stage(1);

    for (int i = 0; i < NK; i++) {
        if (i + 1 < NK) cpwait<1>(); else cpwait<0>();
        __syncthreads();

        const uint32_t Ab = smb + (uint32_t)(i % 3) * 32768u;
        const uint32_t Wb = Ab + 16384u;

        #pragma unroll
        for (int kb = 0; kb < 4; kb++) {
            uint32_t bw[2][4];
            #pragma unroll
            for (int np = 0; np < 2; np++)
                ldsm4(bw[np][0], bw[np][1], bw[np][2], bw[np][3],
                      Wb + (uint32_t)(wn * 32 + np * 16) * 128u + lrow128 + x4[kb]);
            #pragma unroll
            for (int mt = 0; mt < 4; mt++) {
                uint32_t a0, a1, a2, a3;
                ldsm4(a0, a1, a2, a3,
                      Ab + (uint32_t)(wm * 64 + mt * 16) * 128u + lrow128 + x4[kb]);
                #pragma unroll
                for (int nt = 0; nt < 4; nt++) {
                    const int np = nt >> 1, hi = nt & 1;
                    mma_f16(acc[mt][nt][0], acc[mt][nt][1], acc[mt][nt][2], acc[mt][nt][3],
                            a0, a1, a2, a3,
                            bw[np][hi ? 1 : 0], bw[np][hi ? 3 : 2]);
                }
            }
        }

        if (i + 2 < NK) stage(i + 2);
    }

    #pragma unroll
    for (int mt = 0; mt < 4; mt++) {
        const int r = bm + wm * 64 + mt * 16 + g;
        #pragma unroll
        for (int nt = 0; nt < 4; nt++) {
            const int cl = bn + wn * 32 + nt * 8 + 2 * t;
            const float bx = BI[cl], by = BI[cl + 1];
            if (OUTF32) {
                float* Cf = P.Cf;
                *(float2*)(Cf + (size_t)r * P.ldc + cl) =
                    make_float2((acc[mt][nt][0] + bx) * osc, (acc[mt][nt][1] + by) * osc);
                *(float2*)(Cf + (size_t)(r + 8) * P.ldc + cl) =
                    make_float2((acc[mt][nt][2] + bx) * osc, (acc[mt][nt][3] + by) * osc);
            } else {
                __half* Ch = P.Ch[seg];
                *(uint32_t*)(Ch + (size_t)r * P.ldc + cl) =
                    packh2((acc[mt][nt][0] + bx) * osc, (acc[mt][nt][1] + by) * osc);
                *(uint32_t*)(Ch + (size_t)(r + 8) * P.ldc + cl) =
                    packh2((acc[mt][nt][2] + bx) * osc, (acc[mt][nt][3] + by) * osc);
            }
        }
    }
}

// ---------------------------------------------------------------------------
// FP16 flash attention (R8 winner — unchanged).
// ---------------------------------------------------------------------------
struct FlashP {
    const __half *Qp[4], *Kp[4], *Vp[4]; __half* Op[4];
    int sq, skv, so, cmask, cshift;
};

__global__ __launch_bounds__(256, 2) void flash_k(FlashP P)
{
    extern __shared__ char fsm[];
    const uint32_t smb = (uint32_t)__cvta_generic_to_shared(fsm);

    const int z = blockIdx.z;
    const int c = z & P.cmask;
    const int b = z >> P.cshift;
    const int q0 = blockIdx.x * 128;
    const int h  = blockIdx.y;

    const int tid = threadIdx.x;
    const int w = tid >> 5;
    const int lane = tid & 31;
    const int g = lane >> 2;
    const int t = lane & 3;
    const int lr = lane & 15;
    const int lh = lane >> 4;

    const __half* Qb = P.Qp[c] + (size_t)b * SEQL * P.sq  + (size_t)h * 64;
    const __half* Kb = P.Kp[c] + (size_t)b * SEQL * P.skv + (size_t)h * 64;
    const __half* Vb = P.Vp[c] + (size_t)b * SEQL * P.skv + (size_t)h * 64;
    __half*       Ob = P.Op[c] + (size_t)b * SEQL * P.so  + (size_t)h * 64;

    const uint32_t lrow128 = (uint32_t)lr * 128u;
    uint32_t x4[4];
    #pragma unroll
    for (int kb = 0; kb < 4; kb++)
        x4[kb] = (uint32_t)(((kb * 2 + lh) ^ (lr & 7)) << 4);

    {
        const int sr = tid >> 1;
        const int sc = (tid & 1) * 4;
        const __half* src = Qb + (size_t)(q0 + sr) * P.sq + sc * 8;
        #pragma unroll
        for (int cc = 0; cc < 4; cc++)
            cp16(smb + swz(sr, sc + cc), src + cc * 8);
        cpcommit();
    }

    const int kr = tid >> 2;
    const int kc = (tid & 3) * 2;
    auto stageKV = [&](int kt, int s) {
        const __half* pk = Kb + (size_t)(kt + kr) * P.skv + kc * 8;
        const __half* pv = Vb + (size_t)(kt + kr) * P.skv + kc * 8;
        const uint32_t kbase = smb + 16384u + (uint32_t)s * 8192u;
        const uint32_t vbase = smb + 40960u + (uint32_t)s * 8192u;
        cp16(kbase + swz(kr, kc),     pk);
        cp16(kbase + swz(kr, kc + 1), pk + 8);
        cp16(vbase + swz(kr, kc),     pv);
        cp16(vbase + swz(kr, kc + 1), pv + 8);
        cpcommit();
    };

    stageKV(0, 0);
    stageKV(64, 1);
    cpwait<1>();
    __syncthreads();

    uint32_t qa[4][4];
    #pragma unroll
    for (int kb = 0; kb < 4; kb++)
        ldsm4(qa[kb][0], qa[kb][1], qa[kb][2], qa[kb][3],
              smb + (uint32_t)(w * 2048) + lrow128 + x4[kb]);

    float oacc[8][4] = {};
    float mi0 = -INFINITY, mi1 = -INFINITY;
    float li0 = 0.f, li1 = 0.f;

    const uint32_t ONES = 0x3C003C00u;

    const int NT = SEQL / 64;
    for (int it = 0; it < NT; it++) {
        const int s = it % 3;
        const uint32_t Kbase = smb + 16384u + (uint32_t)s * 8192u + lrow128;
        const uint32_t Vbase = smb + 40960u + (uint32_t)s * 8192u + lrow128;

        float sacc[8][4] = {};
        #pragma unroll
        for (int kb = 0; kb < 4; kb++) {
            #pragma unroll
            for (int np = 0; np < 4; np++) {
                uint32_t k0, k1, k2, k3;
                ldsm4(k0, k1, k2, k3, Kbase + (uint32_t)(np * 2048) + x4[kb]);
                mma_f16(sacc[2*np][0], sacc[2*np][1], sacc[2*np][2], sacc[2*np][3],
                        qa[kb][0], qa[kb][1], qa[kb][2], qa[kb][3], k0, k2);
                mma_f16(sacc[2*np+1][0], sacc[2*np+1][1], sacc[2*np+1][2], sacc[2*np+1][3],
                        qa[kb][0], qa[kb][1], qa[kb][2], qa[kb][3], k1, k3);
            }
        }

        uint32_t pa[4][4];
        {
            float mx0 = -INFINITY, mx1 = -INFINITY;
            #pragma unroll
            for (int nt = 0; nt < 8; nt++) {
                mx0 = fmaxf(mx0, fmaxf(sacc[nt][0], sacc[nt][1]));
                mx1 = fmaxf(mx1, fmaxf(sacc[nt][2], sacc[nt][3]));
            }
            mx0 = fmaxf(mx0, __shfl_xor_sync(0xffffffffu, mx0, 1, 4));
            mx0 = fmaxf(mx0, __shfl_xor_sync(0xffffffffu, mx0, 2, 4));
            mx1 = fmaxf(mx1, __shfl_xor_sync(0xffffffffu, mx1, 1, 4));
            mx1 = fmaxf(mx1, __shfl_xor_sync(0xffffffffu, mx1, 2, 4));
            const float mn0 = fmaxf(mi0, mx0);
            const float mn1 = fmaxf(mi1, mx1);
            const float c0 = exp2f(mi0 - mn0);
            const float c1 = exp2f(mi1 - mn1);
            mi0 = mn0; mi1 = mn1;

            float ls[4] = {0.f, 0.f, 0.f, 0.f};
            #pragma unroll
            for (int kb = 0; kb < 4; kb++) {
                __half2 e0 = h2exp2(__floats2half2_rn(sacc[2*kb][0]   - mn0, sacc[2*kb][1]   - mn0));
                __half2 e1 = h2exp2(__floats2half2_rn(sacc[2*kb][2]   - mn1, sacc[2*kb][3]   - mn1));
                __half2 e2 = h2exp2(__floats2half2_rn(sacc[2*kb+1][0] - mn0, sacc[2*kb+1][1] - mn0));
                __half2 e3 = h2exp2(__floats2half2_rn(sacc[2*kb+1][2] - mn1, sacc[2*kb+1][3] - mn1));
                pa[kb][0] = *(uint32_t*)&e0;
                pa[kb][1] = *(uint32_t*)&e1;
                pa[kb][2] = *(uint32_t*)&e2;
                pa[kb][3] = *(uint32_t*)&e3;
                mma_f16(ls[0], ls[1], ls[2], ls[3],
                        pa[kb][0], pa[kb][1], pa[kb][2], pa[kb][3], ONES, ONES);
            }
            li0 = li0 * c0 + ls[0];
            li1 = li1 * c1 + ls[2];

            const bool skip = __all_sync(0xffffffffu, (c0 == 1.0f) & (c1 == 1.0f));
            if (!skip) {
                #pragma unroll
                for (int nt = 0; nt < 8; nt++) {
                    oacc[nt][0] *= c0; oacc[nt][1] *= c0;
                    oacc[nt][2] *= c1; oacc[nt][3] *= c1;
                }
            }
        }

        #pragma unroll
        for (int kb = 0; kb < 4; kb++) {
            #pragma unroll
            for (int np = 0; np < 4; np++) {
                uint32_t v0, v1, v2, v3;
                ldsm4t(v0, v1, v2, v3, Vbase + (uint32_t)(kb * 2048) + x4[np]);
                mma_f16(oacc[2*np][0], oacc[2*np][1], oacc[2*np][2], oacc[2*np][3],
                        pa[kb][0], pa[kb][1], pa[kb][2], pa[kb][3], v0, v1);
                mma_f16(oacc[2*np+1][0], oacc[2*np+1][1], oacc[2*np+1][2], oacc[2*np+1][3],
                        pa[kb][0], pa[kb][1], pa[kb][2], pa[kb][3], v2, v3);
            }
        }

        if (it + 1 < NT) {
            if (it + 2 < NT) { stageKV((it + 2) * 64, (it + 2) % 3); cpwait<1>(); }
            else             { cpwait<0>(); }
            __syncthreads();
        }
    }

    {
        const float inv0 = 1.0f / li0;
        const float inv1 = 1.0f / li1;
        const int r0 = q0 + 16 * w + g;
        #pragma unroll
        for (int nt = 0; nt < 8; nt++) {
            const int col = nt * 8 + 2 * t;
            *(uint32_t*)(Ob + (size_t)r0 * P.so + col) =
                packh2(oacc[nt][0] * inv0, oacc[nt][1] * inv0);
            *(uint32_t*)(Ob + (size_t)(r0 + 8) * P.so + col) =
                packh2(oacc[nt][2] * inv1, oacc[nt][3] * inv1);
        }
    }
}

// ---------------------------------------------------------------------------
extern "C" void kernel_launch(void* const* d_in, const int* in_sizes, int n_in,
                              void* d_out, int out_size)
{
    (void)in_sizes; (void)n_in; (void)out_size;

    const float* hs        = (const float*)d_in[0];
    const float* txt       = (const float*)d_in[1];
    const float* w_q_img   = (const float*)d_in[2];
    const float* b_q_img   = (const float*)d_in[3];
    const float* w_k_img   = (const float*)d_in[4];
    const float* b_k_img   = (const float*)d_in[5];
    const float* w_v_img   = (const float*)d_in[6];
    const float* b_v_img   = (const float*)d_in[7];
    const float* w_q_txt   = (const float*)d_in[8];
    const float* b_q_txt   = (const float*)d_in[9];
    const float* w_k_txt   = (const float*)d_in[10];
    const float* b_k_txt   = (const float*)d_in[11];
    const float* w_v_txt   = (const float*)d_in[12];
    const float* b_v_txt   = (const float*)d_in[13];
    const float* w_out_img = (const float*)d_in[14];
    const float* b_out_img = (const float*)d_in[15];
    const float* w_out_txt = (const float*)d_in[16];
    const float* b_out_txt = (const float*)d_in[17];
    const float* w_cat     = (const float*)d_in[18];
    const float* b_cat     = (const float*)d_in[19];
    const float* in_proj_w = (const float*)d_in[20];
    const float* in_proj_b = (const float*)d_in[21];
    const float* out_proj_w= (const float*)d_in[22];
    const float* out_proj_b= (const float*)d_in[23];
    float* out = (float*)d_out;

    constexpr size_t U  = (size_t)MTOT * HDIM;
    constexpr size_t QW = (size_t)512 * 512;
    const float qsc = 0.125f * 1.4426950408889634f;  // (1/sqrt(64))*log2(e)

    __half* S;
    cudaGetSymbolAddress((void**)&S, g_scratch);
    float* zb;
    cudaGetSymbolAddress((void**)&zb, zbias);

    __half* HSh    = S;
    __half* TXTh   = S + U;
    __half* QKV0h  = S + 2 * U;
    __half* QKV1h  = S + 5 * U;
    __half* C0     = S + 8 * U;
    __half* C1     = S + 9 * U;
    __half* C2     = S + 10 * U;
    __half* C3     = S + 11 * U;
    __half* WCOMB  = S + 12 * U;              // [512 x 1024] half
    __half* WOIT   = WCOMB + 512 * 1024;      // [512 x 512] half (w_out_img^T)
    __half* WOTT   = WOIT + QW;               // [512 x 512] half (w_out_txt^T)
    float*  BCOMB  = (float*)(S + 13 * U);    // [512] fp32
    __half* OUTBh  = S + 14 * U;
    __half* QKV2h  = S + 15 * U;
    __half* CTXh   = S + 18 * U;
    __half* WB     = S + 19 * U;
    __half* whqi = WB;           __half* whki = WB + QW;     __half* whvi = WB + 2 * QW;
    __half* whqt = WB + 3 * QW;  __half* whkt = WB + 4 * QW; __half* whvt = WB + 5 * QW;
    __half* whop = WB + 6 * QW;
    __half* whcat = WB + 7 * QW;            // 512*1024
    __half* whinp = whcat + 512 * 1024;     // 1536*512

    const int GSM = 98304, FSM = 65536;
    cudaFuncSetAttribute(gemm_k<0,false>, cudaFuncAttributeMaxDynamicSharedMemorySize, GSM);
    cudaFuncSetAttribute(gemm_k<1,false>, cudaFuncAttributeMaxDynamicSharedMemorySize, GSM);
    cudaFuncSetAttribute(gemm_k<0,true>,  cudaFuncAttributeMaxDynamicSharedMemorySize, GSM);
    cudaFuncSetAttribute(flash_k,         cudaFuncAttributeMaxDynamicSharedMemorySize, FSM);

    // 0) fp32 -> fp16 conversions (inputs + weights)
    {
        CvtP p;
        const float* srcs[11] = {hs, txt, w_q_img, w_k_img, w_v_img, w_q_txt, w_k_txt,
                                 w_v_txt, out_proj_w, w_cat, in_proj_w};
        __half* dsts[11] = {HSh, TXTh, whqi, whki, whvi, whqt, whkt,
                            whvt, whop, whcat, whinp};
        int ns[11] = {(int)U, (int)U, (int)QW, (int)QW, (int)QW, (int)QW, (int)QW,
                      (int)QW, (int)QW, 512*1024, 1536*512};
        int tot = 0;
        for (int i = 0; i < 11; i++) { p.src[i]=srcs[i]; p.dst[i]=dsts[i]; p.nblk[i]=ns[i]/1024; tot+=ns[i]/1024; }
        // pad remaining table entries
        for (int i = 11; i < 13; i++) { p.src[i]=srcs[0]; p.dst[i]=dsts[0]; p.nblk[i]=0; }
        cvt_k<<<tot, 256>>>(p);
    }

    // 0b) transpose+cvt w_out_img / w_out_txt
    {
        TrP p;
        p.src[0] = w_out_img; p.dst[0] = WOIT;
        p.src[1] = w_out_txt; p.dst[1] = WOTT;
        tcv_k<<<dim3(16, 16, 2), dim3(32, 8)>>>(p);
    }

    // 0c) prep gemm: WCOMB[:, :512] = wcat_L @ w_oi, WCOMB[:, 512:] = wcat_R @ w_ot
    {
        GemmP p = {};
        p.A1[0] = whcat;       p.A1[1] = whcat + 512;
        p.W[0]  = WOIT;        p.W[1]  = WOTT;
        p.Bi[0] = zb;          p.Bi[1] = zb;
        p.Ch[0] = WCOMB;       p.Ch[1] = WCOMB + 512;
        p.osc[0] = p.osc[1] = 1.f;
        p.lda = 1024; p.ldc = 1024; p.K = 512; p.KA = 512;
        gemm_k<0,false><<<dim3(8, 4), dim3(256), GSM>>>(p);
    }

    // 0d) combined bias
    biascomb_k<<<512, 256>>>(w_cat, b_out_img, b_out_txt, b_cat, BCOMB);

    const dim3 blk(256);

    // 1) QKV projections (two launches, as R8), Q pre-scaled
    {
        GemmP p = {};
        p.A1[0] = p.A1[1] = p.A1[2] = HSh;
        p.W[0] = whqi; p.W[1] = whki; p.W[2] = whvi;
        p.Bi[0] = b_q_img; p.Bi[1] = b_k_img; p.Bi[2] = b_v_img;
        p.Ch[0] = QKV0h; p.Ch[1] = QKV0h + 512; p.Ch[2] = QKV0h + 1024;
        p.osc[0] = qsc; p.osc[1] = 1.f; p.osc[2] = 1.f;
        p.lda = HDIM; p.ldc = 3 * HDIM; p.K = HDIM; p.KA = HDIM;
        gemm_k<0,false><<<dim3(12, 64), blk, GSM>>>(p);
        p.A1[0] = p.A1[1] = p.A1[2] = TXTh;
        p.W[0] = whqt; p.W[1] = whkt; p.W[2] = whvt;
        p.Bi[0] = b_q_txt; p.Bi[1] = b_k_txt; p.Bi[2] = b_v_txt;
        p.Ch[0] = QKV1h; p.Ch[1] = QKV1h + 512; p.Ch[2] = QKV1h + 1024;
        gemm_k<0,false><<<dim3(12, 64), blk, GSM>>>(p);
    }

    // 2) four attentions in one launch
    {
        FlashP p;
        p.Qp[0] = QKV0h; p.Kp[0] = QKV0h + 512; p.Vp[0] = QKV0h + 1024; p.Op[0] = C0;
        p.Qp[1] = QKV1h; p.Kp[1] = QKV1h + 512; p.Vp[1] = QKV1h + 1024; p.Op[1] = C1;
        p.Qp[2] = QKV0h; p.Kp[2] = QKV1h + 512; p.Vp[2] = QKV1h + 1024; p.Op[2] = C2;
        p.Qp[3] = QKV1h; p.Kp[3] = QKV0h + 512; p.Vp[3] = QKV0h + 1024; p.Op[3] = C3;
        p.sq = 3 * HDIM; p.skv = 3 * HDIM; p.so = HDIM; p.cmask = 3; p.cshift = 2;
        flash_k<<<dim3(SEQL / 128, 8, BATCH * 4), blk, FSM>>>(p);
    }

    // 3) combined out+cat gemm: OUTB = 0.5(C0+C2)@W1'^T + 0.5(C1+C3)@W2'^T + b'
    {
        GemmP p = {};
        p.A1[0] = C0; p.A2[0] = C2;
        p.A1b[0] = C1; p.A2b[0] = C3;
        p.W[0] = WCOMB; p.Bi[0] = BCOMB;
        p.Ch[0] = OUTBh; p.osc[0] = 1.f;
        p.lda = HDIM; p.ldc = HDIM; p.K = 1024; p.KA = 512;
        gemm_k<1,false><<<dim3(4, 64), blk, GSM>>>(p);
    }

    // 4) pooling in_proj, Q pre-scaled
    {
        GemmP p = {};
        p.A1[0] = p.A1[1] = p.A1[2] = OUTBh;
        p.W[0] = whinp; p.W[1] = whinp + 512 * 512; p.W[2] = whinp + 1024 * 512;
        p.Bi[0] = in_proj_b; p.Bi[1] = in_proj_b + 512; p.Bi[2] = in_proj_b + 1024;
        p.Ch[0] = QKV2h; p.Ch[1] = QKV2h + 512; p.Ch[2] = QKV2h + 1024;
        p.osc[0] = qsc; p.osc[1] = 1.f; p.osc[2] = 1.f;
        p.lda = HDIM; p.ldc = 3 * HDIM; p.K = HDIM; p.KA = HDIM;
        gemm_k<0,false><<<dim3(12, 64), blk, GSM>>>(p);
    }

    // 5) pooling self-attention
    {
        FlashP p;
        p.Qp[0] = QKV2h; p.Kp[0] = QKV2h + 512; p.Vp[0] = QKV2h + 1024; p.Op[0] = CTXh;
        p.Qp[1] = p.Qp[2] = p.Qp[3] = QKV2h;
        p.Kp[1] = p.Kp[2] = p.Kp[3] = QKV2h + 512;
        p.Vp[1] = p.Vp[2] = p.Vp[3] = QKV2h + 1024;
        p.Op[1] = p.Op[2] = p.Op[3] = CTXh;
        p.sq = 3 * HDIM; p.skv = 3 * HDIM; p.so = HDIM; p.cmask = 0; p.cshift = 0;
        flash_k<<<dim3(SEQL / 128, 8, BATCH), blk, FSM>>>(p);
    }

    // 6) out_proj -> fp32 output
    {
        GemmP p = {};
        p.A1[0] = CTXh; p.W[0] = whop; p.Bi[0] = out_proj_b;
        p.Cf = out; p.osc[0] = 1.f;
        p.lda = HDIM; p.ldc = HDIM; p.K = HDIM; p.KA = HDIM;
        gemm_k<0,true><<<dim3(4, 64), blk, GSM>>>(p);
    }
}

// round 12
// speedup vs baseline: 1.1522x; 1.0381x over previous
#include <cuda_runtime.h>
#include <cuda_fp16.h>
#include <math.h>
#include <stdint.h>

#define HDIM 512
#define BATCH 8
#define SEQL 1024
#define MTOT 8192

// half scratch: 84M halves = 168MB
__device__ __half g_scratch[(size_t)84 * 1024 * 1024];
__device__ float zbias[512] = {};   // zero bias for prep gemm

// ---------------------------------------------------------------------------
// Primitives
// ---------------------------------------------------------------------------
__device__ __forceinline__ void mma_f16(float& d0, float& d1, float& d2, float& d3,
                                        uint32_t a0, uint32_t a1, uint32_t a2, uint32_t a3,
                                        uint32_t b0, uint32_t b1)
{
    asm volatile(
        "mma.sync.aligned.m16n8k16.row.col.f32.f16.f16.f32 "
        "{%0,%1,%2,%3}, {%4,%5,%6,%7}, {%8,%9}, {%0,%1,%2,%3};"
        : "+f"(d0), "+f"(d1), "+f"(d2), "+f"(d3)
        : "r"(a0), "r"(a1), "r"(a2), "r"(a3), "r"(b0), "r"(b1));
}

__device__ __forceinline__ void ldsm4(uint32_t& r0, uint32_t& r1, uint32_t& r2, uint32_t& r3,
                                      uint32_t addr)
{
    asm volatile("ldmatrix.sync.aligned.m8n8.x4.shared.b16 {%0,%1,%2,%3}, [%4];"
                 : "=r"(r0), "=r"(r1), "=r"(r2), "=r"(r3) : "r"(addr));
}
__device__ __forceinline__ void ldsm4t(uint32_t& r0, uint32_t& r1, uint32_t& r2, uint32_t& r3,
                                       uint32_t addr)
{
    asm volatile("ldmatrix.sync.aligned.m8n8.x4.trans.shared.b16 {%0,%1,%2,%3}, [%4];"
                 : "=r"(r0), "=r"(r1), "=r"(r2), "=r"(r3) : "r"(addr));
}

__device__ __forceinline__ void cp16(uint32_t dst, const void* src) {
    asm volatile("cp.async.cg.shared.global [%0], [%1], 16;" :: "r"(dst), "l"(src));
}
__device__ __forceinline__ void cpcommit() { asm volatile("cp.async.commit_group;"); }
template<int N> __device__ __forceinline__ void cpwait() {
    asm volatile("cp.async.wait_group %0;" :: "n"(N));
}

// XOR swizzle: rows of 128B (64 halves), 16B chunk c in 0..7
__device__ __forceinline__ uint32_t swz(uint32_t r, uint32_t c) {
    return r * 128u + ((c ^ (r & 7u)) << 4);
}

__device__ __forceinline__ uint32_t packh2(float x, float y) {
    __half2 h = __floats2half2_rn(x, y);
    return *(uint32_t*)&h;
}

// ---------------------------------------------------------------------------
// fp32 -> fp16 conversion kernel
// ---------------------------------------------------------------------------
struct CvtP { const float* src[11]; __half* dst[11]; int nblk[11]; };

__global__ __launch_bounds__(256) void cvt_k(CvtP P)
{
    int b = blockIdx.x;
    int s = 0;
    while (b >= P.nblk[s]) { b -= P.nblk[s]; ++s; }
    size_t i = ((size_t)b * 256 + threadIdx.x) * 4;
    float4 v = *(const float4*)(P.src[s] + i);
    uint2 o;
    o.x = packh2(v.x, v.y);
    o.y = packh2(v.z, v.w);
    *(uint2*)(P.dst[s] + i) = o;
}

// ---------------------------------------------------------------------------
// transpose + cvt: dst[n,k] = fp16(src[k,n]) for 512x512 fp32 matrices
// ---------------------------------------------------------------------------
struct TrP { const float* src[2]; __half* dst[2]; };

__global__ void tcv_k(TrP P)
{
    __shared__ __half tile[32][33];
    const int s = blockIdx.z;
    const int x = blockIdx.x * 32, y = blockIdx.y * 32;
    const int tx = threadIdx.x, ty = threadIdx.y;
    const float* src = P.src[s];
    #pragma unroll
    for (int r = ty; r < 32; r += 8)
        tile[r][tx] = __float2half_rn(src[(size_t)(y + r) * 512 + x + tx]);
    __syncthreads();
    __half* dst = P.dst[s];
    #pragma unroll
    for (int r = ty; r < 32; r += 8)
        dst[(size_t)(x + r) * 512 + y + tx] = tile[tx][r];
}

// ---------------------------------------------------------------------------
// bias combine (fp16 wcat): bout[n] = bcat[n] + sum_j wcat_h[n,j]*([boi;bot])[j]
// ---------------------------------------------------------------------------
__global__ void biascomb_k(const __half* __restrict__ wcat,
                           const float* __restrict__ boi,
                           const float* __restrict__ bot,
                           const float* __restrict__ bcat,
                           float* __restrict__ bout)
{
    __shared__ float red[256];
    const int n = blockIdx.x;
    float s = 0.f;
    for (int j = threadIdx.x; j < 1024; j += 256) {
        const float b = (j < 512) ? boi[j] : bot[j - 512];
        s += __half2float(wcat[(size_t)n * 1024 + j]) * b;
    }
    red[threadIdx.x] = s;
    __syncthreads();
    #pragma unroll
    for (int o = 128; o; o >>= 1) {
        if (threadIdx.x < o) red[threadIdx.x] += red[threadIdx.x + o];
        __syncthreads();
    }
    if (threadIdx.x == 0) bout[n] = red[0] + bcat[n];
}

// ---------------------------------------------------------------------------
// FP16 GEMM (NT): C = A @ W^T + bias, times per-seg osc. Pure cp.async A path.
// CTA tile 128x128, BK=64, 256 thr (8 warps 2x4, warp tile 64x32).
// 3-stage cp.async pipeline (96KB smem), single sync/iter, XOR swizzle.
// Up to 6 per-512-col segments.
// ---------------------------------------------------------------------------
struct GemmP {
    const __half* A1[6];
    const __half* W[6]; const float* Bi[6];
    __half* Ch[6]; float* Cf;
    float osc[6];
    int lda, ldc, K;
};

template<bool OUTF32>
__global__ __launch_bounds__(256, 2) void gemm_k(GemmP P)
{
    extern __shared__ char sm[];
    const uint32_t smb = (uint32_t)__cvta_generic_to_shared(sm);

    const int bm  = blockIdx.y * 128;
    const int bnG = blockIdx.x * 128;
    const int seg = bnG >> 9;
    const int bn  = bnG & 511;
    const __half* A1 = P.A1[seg];
    const __half* W  = P.W[seg];
    const float*  BI = P.Bi[seg];
    const float  osc = P.osc[seg];

    const int tid  = threadIdx.x;
    const int warp = tid >> 5;
    const int lane = tid & 31;
    const int g = lane >> 2;
    const int t = lane & 3;
    const int wm = warp >> 2;
    const int wn = warp & 3;
    const int lr = lane & 15;
    const int lh = lane >> 4;

    const int sr = tid >> 1;
    const int sc = (tid & 1) * 4;

    const uint32_t lrow128 = (uint32_t)lr * 128u;
    uint32_t x4[4];
    #pragma unroll
    for (int kb = 0; kb < 4; kb++)
        x4[kb] = (uint32_t)(((kb * 2 + lh) ^ (lr & 7)) << 4);

    const int NK = P.K >> 6;
    float acc[4][4][4] = {};

    auto stage = [&](int i) {
        const uint32_t da = smb + (uint32_t)(i % 3) * 32768u;
        const __half* sa = A1 + (size_t)(bm + sr) * P.lda + i * 64 + sc * 8;
        const __half* sw = W  + (size_t)(bn + sr) * P.K + i * 64 + sc * 8;
        #pragma unroll
        for (int c = 0; c < 4; c++) {
            cp16(da + swz(sr, sc + c), sa + c * 8);
            cp16(da + 16384u + swz(sr, sc + c), sw + c * 8);
        }
        cpcommit();
    };

    stage(0);
    if (NK > 1) stage(1);

    for (int i = 0; i < NK; i++) {
        if (i + 1 < NK) cpwait<1>(); else cpwait<0>();
        __syncthreads();

        const uint32_t Ab = smb + (uint32_t)(i % 3) * 32768u;
        const uint32_t Wb = Ab + 16384u;

        #pragma unroll
        for (int kb = 0; kb < 4; kb++) {
            uint32_t bw[2][4];
            #pragma unroll
            for (int np = 0; np < 2; np++)
                ldsm4(bw[np][0], bw[np][1], bw[np][2], bw[np][3],
                      Wb + (uint32_t)(wn * 32 + np * 16) * 128u + lrow128 + x4[kb]);
            #pragma unroll
            for (int mt = 0; mt < 4; mt++) {
                uint32_t a0, a1, a2, a3;
                ldsm4(a0, a1, a2, a3,
                      Ab + (uint32_t)(wm * 64 + mt * 16) * 128u + lrow128 + x4[kb]);
                #pragma unroll
                for (int nt = 0; nt < 4; nt++) {
                    const int np = nt >> 1, hi = nt & 1;
                    mma_f16(acc[mt][nt][0], acc[mt][nt][1], acc[mt][nt][2], acc[mt][nt][3],
                            a0, a1, a2, a3,
                            bw[np][hi ? 1 : 0], bw[np][hi ? 3 : 2]);
                }
            }
        }

        if (i + 2 < NK) stage(i + 2);
    }

    #pragma unroll
    for (int mt = 0; mt < 4; mt++) {
        const int r = bm + wm * 64 + mt * 16 + g;
        #pragma unroll
        for (int nt = 0; nt < 4; nt++) {
            const int cl = bn + wn * 32 + nt * 8 + 2 * t;
            const float bx = BI[cl], by = BI[cl + 1];
            if (OUTF32) {
                float* Cf = P.Cf;
                *(float2*)(Cf + (size_t)r * P.ldc + cl) =
                    make_float2((acc[mt][nt][0] + bx) * osc, (acc[mt][nt][1] + by) * osc);
                *(float2*)(Cf + (size_t)(r + 8) * P.ldc + cl) =
                    make_float2((acc[mt][nt][2] + bx) * osc, (acc[mt][nt][3] + by) * osc);
            } else {
                __half* Ch = P.Ch[seg];
                *(uint32_t*)(Ch + (size_t)r * P.ldc + cl) =
                    packh2((acc[mt][nt][0] + bx) * osc, (acc[mt][nt][1] + by) * osc);
                *(uint32_t*)(Ch + (size_t)(r + 8) * P.ldc + cl) =
                    packh2((acc[mt][nt][2] + bx) * osc, (acc[mt][nt][3] + by) * osc);
            }
        }
    }
}

// ---------------------------------------------------------------------------
// FP16 flash attention. DUAL: two KV streams against the same Q; the phase-A
// normalized output (x0.5) is stashed in smem (warp-private rows, no sync),
// phase B runs on KV2, epilogue writes 0.5*(Oa/la + Ob/lb).
// Inner loop identical to the R8 winner.
// ---------------------------------------------------------------------------
struct FlashP {
    const __half *Qp[4], *Kp[4], *Vp[4], *Kp2[4], *Vp2[4]; __half* Op[4];
    int sq, skv, so, cmask, cshift;
};

#define OS_STRIDE 68

template<bool DUAL>
__global__ __launch_bounds__(256, 2) void flash_k(FlashP P)
{
    extern __shared__ char fsm[];
    const uint32_t smb = (uint32_t)__cvta_generic_to_shared(fsm);
    // Q @0 (16KB), K[s] @16384+s*8192 (3), V[s] @40960+s*8192 (3);
    // DUAL: stash @65536 (128 x OS_STRIDE fp32)

    const int z = blockIdx.z;
    const int c = z & P.cmask;
    const int b = z >> P.cshift;
    const int q0 = blockIdx.x * 128;
    const int h  = blockIdx.y;

    const int tid = threadIdx.x;
    const int w = tid >> 5;
    const int lane = tid & 31;
    const int g = lane >> 2;
    const int t = lane & 3;
    const int lr = lane & 15;
    const int lh = lane >> 4;

    const __half* Qb  = P.Qp[c] + (size_t)b * SEQL * P.sq  + (size_t)h * 64;
    const __half* Kb  = P.Kp[c] + (size_t)b * SEQL * P.skv + (size_t)h * 64;
    const __half* Vb  = P.Vp[c] + (size_t)b * SEQL * P.skv + (size_t)h * 64;
    const __half* Kb2 = DUAL ? P.Kp2[c] + (size_t)b * SEQL * P.skv + (size_t)h * 64 : nullptr;
    const __half* Vb2 = DUAL ? P.Vp2[c] + (size_t)b * SEQL * P.skv + (size_t)h * 64 : nullptr;
    __half*       Ob  = P.Op[c] + (size_t)b * SEQL * P.so  + (size_t)h * 64;

    const uint32_t lrow128 = (uint32_t)lr * 128u;
    uint32_t x4[4];
    #pragma unroll
    for (int kb = 0; kb < 4; kb++)
        x4[kb] = (uint32_t)(((kb * 2 + lh) ^ (lr & 7)) << 4);

    {
        const int sr = tid >> 1;
        const int sc = (tid & 1) * 4;
        const __half* src = Qb + (size_t)(q0 + sr) * P.sq + sc * 8;
        #pragma unroll
        for (int cc = 0; cc < 4; cc++)
            cp16(smb + swz(sr, sc + cc), src + cc * 8);
        cpcommit();
    }

    const int kr = tid >> 2;
    const int kc = (tid & 3) * 2;
    auto stageKV = [&](int tile) {
        const int s = tile % 3;
        const int kt = (DUAL ? (tile & 15) : tile) * 64;
        const __half* pk0 = (DUAL && (tile >> 4)) ? Kb2 : Kb;
        const __half* pv0 = (DUAL && (tile >> 4)) ? Vb2 : Vb;
        const __half* pk = pk0 + (size_t)(kt + kr) * P.skv + kc * 8;
        const __half* pv = pv0 + (size_t)(kt + kr) * P.skv + kc * 8;
        const uint32_t kbase = smb + 16384u + (uint32_t)s * 8192u;
        const uint32_t vbase = smb + 40960u + (uint32_t)s * 8192u;
        cp16(kbase + swz(kr, kc),     pk);
        cp16(kbase + swz(kr, kc + 1), pk + 8);
        cp16(vbase + swz(kr, kc),     pv);
        cp16(vbase + swz(kr, kc + 1), pv + 8);
        cpcommit();
    };

    stageKV(0);
    stageKV(1);
    cpwait<1>();
    __syncthreads();

    uint32_t qa[4][4];
    #pragma unroll
    for (int kb = 0; kb < 4; kb++)
        ldsm4(qa[kb][0], qa[kb][1], qa[kb][2], qa[kb][3],
              smb + (uint32_t)(w * 2048) + lrow128 + x4[kb]);

    float oacc[8][4] = {};
    float mi0 = -INFINITY, mi1 = -INFINITY;
    float li0 = 0.f, li1 = 0.f;

    const uint32_t ONES = 0x3C003C00u;
    float* Os = (float*)(fsm + 65536);
    const int rr = 16 * w + g;

    const int NT = DUAL ? 32 : 16;
    for (int it = 0; it < NT; it++) {
        const int s = it % 3;
        const uint32_t Kbase = smb + 16384u + (uint32_t)s * 8192u + lrow128;
        const uint32_t Vbase = smb + 40960u + (uint32_t)s * 8192u + lrow128;

        float sacc[8][4] = {};
        #pragma unroll
        for (int kb = 0; kb < 4; kb++) {
            #pragma unroll
            for (int np = 0; np < 4; np++) {
                uint32_t k0, k1, k2, k3;
                ldsm4(k0, k1, k2, k3, Kbase + (uint32_t)(np * 2048) + x4[kb]);
                mma_f16(sacc[2*np][0], sacc[2*np][1], sacc[2*np][2], sacc[2*np][3],
                        qa[kb][0], qa[kb][1], qa[kb][2], qa[kb][3], k0, k2);
                mma_f16(sacc[2*np+1][0], sacc[2*np+1][1], sacc[2*np+1][2], sacc[2*np+1][3],
                        qa[kb][0], qa[kb][1], qa[kb][2], qa[kb][3], k1, k3);
            }
        }

        uint32_t pa[4][4];
        {
            float mx0 = -INFINITY, mx1 = -INFINITY;
            #pragma unroll
            for (int nt = 0; nt < 8; nt++) {
                mx0 = fmaxf(mx0, fmaxf(sacc[nt][0], sacc[nt][1]));
                mx1 = fmaxf(mx1, fmaxf(sacc[nt][2], sacc[nt][3]));
            }
            mx0 = fmaxf(mx0, __shfl_xor_sync(0xffffffffu, mx0, 1, 4));
            mx0 = fmaxf(mx0, __shfl_xor_sync(0xffffffffu, mx0, 2, 4));
            mx1 = fmaxf(mx1, __shfl_xor_sync(0xffffffffu, mx1, 1, 4));
            mx1 = fmaxf(mx1, __shfl_xor_sync(0xffffffffu, mx1, 2, 4));
            const float mn0 = fmaxf(mi0, mx0);
            const float mn1 = fmaxf(mi1, mx1);
            const float c0 = exp2f(mi0 - mn0);
            const float c1 = exp2f(mi1 - mn1);
            mi0 = mn0; mi1 = mn1;

            float ls[4] = {0.f, 0.f, 0.f, 0.f};
            #pragma unroll
            for (int kb = 0; kb < 4; kb++) {
                __half2 e0 = h2exp2(__floats2half2_rn(sacc[2*kb][0]   - mn0, sacc[2*kb][1]   - mn0));
                __half2 e1 = h2exp2(__floats2half2_rn(sacc[2*kb][2]   - mn1, sacc[2*kb][3]   - mn1));
                __half2 e2 = h2exp2(__floats2half2_rn(sacc[2*kb+1][0] - mn0, sacc[2*kb+1][1] - mn0));
                __half2 e3 = h2exp2(__floats2half2_rn(sacc[2*kb+1][2] - mn1, sacc[2*kb+1][3] - mn1));
                pa[kb][0] = *(uint32_t*)&e0;
                pa[kb][1] = *(uint32_t*)&e1;
                pa[kb][2] = *(uint32_t*)&e2;
                pa[kb][3] = *(uint32_t*)&e3;
                mma_f16(ls[0], ls[1], ls[2], ls[3],
                        pa[kb][0], pa[kb][1], pa[kb][2], pa[kb][3], ONES, ONES);
            }
            li0 = li0 * c0 + ls[0];
            li1 = li1 * c1 + ls[2];

            const bool skip = __all_sync(0xffffffffu, (c0 == 1.0f) & (c1 == 1.0f));
            if (!skip) {
                #pragma unroll
                for (int nt = 0; nt < 8; nt++) {
                    oacc[nt][0] *= c0; oacc[nt][1] *= c0;
                    oacc[nt][2] *= c1; oacc[nt][3] *= c1;
                }
            }
        }

        #pragma unroll
        for (int kb = 0; kb < 4; kb++) {
            #pragma unroll
            for (int np = 0; np < 4; np++) {
                uint32_t v0, v1, v2, v3;
                ldsm4t(v0, v1, v2, v3, Vbase + (uint32_t)(kb * 2048) + x4[np]);
                mma_f16(oacc[2*np][0], oacc[2*np][1], oacc[2*np][2], oacc[2*np][3],
                        pa[kb][0], pa[kb][1], pa[kb][2], pa[kb][3], v0, v1);
                mma_f16(oacc[2*np+1][0], oacc[2*np+1][1], oacc[2*np+1][2], oacc[2*np+1][3],
                        pa[kb][0], pa[kb][1], pa[kb][2], pa[kb][3], v2, v3);
            }
        }

        // DUAL phase boundary: stash normalized phase-A output, reset stats
        if (DUAL && it == 15) {
            const float s0 = 0.5f / li0;
            const float s1 = 0.5f / li1;
            #pragma unroll
            for (int nt = 0; nt < 8; nt++) {
                const int col = nt * 8 + 2 * t;
                Os[rr * OS_STRIDE + col]           = oacc[nt][0] * s0;
                Os[rr * OS_STRIDE + col + 1]       = oacc[nt][1] * s0;
                Os[(rr + 8) * OS_STRIDE + col]     = oacc[nt][2] * s1;
                Os[(rr + 8) * OS_STRIDE + col + 1] = oacc[nt][3] * s1;
                oacc[nt][0] = oacc[nt][1] = oacc[nt][2] = oacc[nt][3] = 0.f;
            }
            mi0 = mi1 = -INFINITY;
            li0 = li1 = 0.f;
        }

        if (it + 1 < NT) {
            if (it + 2 < NT) { stageKV(it + 2); cpwait<1>(); }
            else             { cpwait<0>(); }
            __syncthreads();
        }
    }

    // epilogue
    if (DUAL) {
        const float inv0 = 0.5f / li0;
        const float inv1 = 0.5f / li1;
        const int r0 = q0 + rr;
        #pragma unroll
        for (int nt = 0; nt < 8; nt++) {
            const int col = nt * 8 + 2 * t;
            float o00 = Os[rr * OS_STRIDE + col]           + oacc[nt][0] * inv0;
            float o01 = Os[rr * OS_STRIDE + col + 1]       + oacc[nt][1] * inv0;
            float o10 = Os[(rr + 8) * OS_STRIDE + col]     + oacc[nt][2] * inv1;
            float o11 = Os[(rr + 8) * OS_STRIDE + col + 1] + oacc[nt][3] * inv1;
            *(uint32_t*)(Ob + (size_t)r0 * P.so + col)       = packh2(o00, o01);
            *(uint32_t*)(Ob + (size_t)(r0 + 8) * P.so + col) = packh2(o10, o11);
        }
    } else {
        const float inv0 = 1.0f / li0;
        const float inv1 = 1.0f / li1;
        const int r0 = q0 + rr;
        #pragma unroll
        for (int nt = 0; nt < 8; nt++) {
            const int col = nt * 8 + 2 * t;
            *(uint32_t*)(Ob + (size_t)r0 * P.so + col) =
                packh2(oacc[nt][0] * inv0, oacc[nt][1] * inv0);
            *(uint32_t*)(Ob + (size_t)(r0 + 8) * P.so + col) =
                packh2(oacc[nt][2] * inv1, oacc[nt][3] * inv1);
        }
    }
}

// ---------------------------------------------------------------------------
extern "C" void kernel_launch(void* const* d_in, const int* in_sizes, int n_in,
                              void* d_out, int out_size)
{
    (void)in_sizes; (void)n_in; (void)out_size;

    const float* hs        = (const float*)d_in[0];
    const float* txt       = (const float*)d_in[1];
    const float* w_q_img   = (const float*)d_in[2];
    const float* b_q_img   = (const float*)d_in[3];
    const float* w_k_img   = (const float*)d_in[4];
    const float* b_k_img   = (const float*)d_in[5];
    const float* w_v_img   = (const float*)d_in[6];
    const float* b_v_img   = (const float*)d_in[7];
    const float* w_q_txt   = (const float*)d_in[8];
    const float* b_q_txt   = (const float*)d_in[9];
    const float* w_k_txt   = (const float*)d_in[10];
    const float* b_k_txt   = (const float*)d_in[11];
    const float* w_v_txt   = (const float*)d_in[12];
    const float* b_v_txt   = (const float*)d_in[13];
    const float* w_out_img = (const float*)d_in[14];
    const float* b_out_img = (const float*)d_in[15];
    const float* w_out_txt = (const float*)d_in[16];
    const float* b_out_txt = (const float*)d_in[17];
    const float* w_cat     = (const float*)d_in[18];
    const float* b_cat     = (const float*)d_in[19];
    const float* in_proj_w = (const float*)d_in[20];
    const float* in_proj_b = (const float*)d_in[21];
    const float* out_proj_w= (const float*)d_in[22];
    const float* out_proj_b= (const float*)d_in[23];
    float* out = (float*)d_out;

    constexpr size_t U  = (size_t)MTOT * HDIM;      // 4.19M halves
    constexpr size_t QW = (size_t)512 * 512;
    const float qsc = 0.125f * 1.4426950408889634f; // (1/sqrt(64))*log2(e)

    __half* S;
    cudaGetSymbolAddress((void**)&S, g_scratch);
    float* zb;
    cudaGetSymbolAddress((void**)&zb, zbias);

    __half* HSh    = S;
    __half* TXTh   = S + U;
    __half* QKV0h  = S + 2 * U;
    __half* QKV1h  = S + 5 * U;
    __half* OUTC   = S + 8 * U;               // [8192 x 1024] half
    __half* WCOMB  = S + 10 * U;              // [512 x 1024]
    __half* WOIT   = WCOMB + 512 * 1024;      // [512 x 512]
    __half* WOTT   = WOIT + QW;               // [512 x 512]
    float*  BCOMB  = (float*)(WOTT + QW);     // [512] fp32
    __half* OUTBh  = S + 11 * U;
    __half* QKV2h  = S + 12 * U;
    __half* CTXh   = S + 15 * U;
    __half* WB     = S + 16 * U;
    __half* whqi = WB;           __half* whki = WB + QW;     __half* whvi = WB + 2 * QW;
    __half* whqt = WB + 3 * QW;  __half* whkt = WB + 4 * QW; __half* whvt = WB + 5 * QW;
    __half* whop = WB + 6 * QW;
    __half* whcat = WB + 7 * QW;            // 512*1024
    __half* whinp = whcat + 512 * 1024;     // 1536*512

    const int GSM   = 98304;
    const int FSM_S = 65536;
    const int FSM_D = 65536 + 128 * OS_STRIDE * 4;   // +34816
    cudaFuncSetAttribute(gemm_k<false>,  cudaFuncAttributeMaxDynamicSharedMemorySize, GSM);
    cudaFuncSetAttribute(gemm_k<true>,   cudaFuncAttributeMaxDynamicSharedMemorySize, GSM);
    cudaFuncSetAttribute(flash_k<false>, cudaFuncAttributeMaxDynamicSharedMemorySize, FSM_S);
    cudaFuncSetAttribute(flash_k<true>,  cudaFuncAttributeMaxDynamicSharedMemorySize, FSM_D);

    // 0) fp32 -> fp16 conversions
    {
        CvtP p;
        const float* srcs[11] = {hs, txt, w_q_img, w_k_img, w_v_img, w_q_txt, w_k_txt,
                                 w_v_txt, out_proj_w, w_cat, in_proj_w};
        __half* dsts[11] = {HSh, TXTh, whqi, whki, whvi, whqt, whkt,
                            whvt, whop, whcat, whinp};
        int ns[11] = {(int)U, (int)U, (int)QW, (int)QW, (int)QW, (int)QW, (int)QW,
                      (int)QW, (int)QW, 512*1024, 1536*512};
        int tot = 0;
        for (int i = 0; i < 11; i++) { p.src[i]=srcs[i]; p.dst[i]=dsts[i]; p.nblk[i]=ns[i]/1024; tot+=ns[i]/1024; }
        cvt_k<<<tot, 256>>>(p);
    }

    // 0b) transpose+cvt w_out_img / w_out_txt
    {
        TrP p;
        p.src[0] = w_out_img; p.dst[0] = WOIT;
        p.src[1] = w_out_txt; p.dst[1] = WOTT;
        tcv_k<<<dim3(16, 16, 2), dim3(32, 8)>>>(p);
    }

    // 0c) prep gemm: WCOMB = [wcat_L @ w_oi | wcat_R @ w_ot]
    {
        GemmP p = {};
        p.A1[0] = whcat;  p.A1[1] = whcat + 512;
        p.W[0]  = WOIT;   p.W[1]  = WOTT;
        p.Bi[0] = zb;     p.Bi[1] = zb;
        p.Ch[0] = WCOMB;  p.Ch[1] = WCOMB + 512;
        p.osc[0] = p.osc[1] = 1.f;
        p.lda = 1024; p.ldc = 1024; p.K = 512;
        gemm_k<false><<<dim3(8, 4), dim3(256), GSM>>>(p);
    }

    // 0d) combined bias (fp16 wcat)
    biascomb_k<<<512, 256>>>(whcat, b_out_img, b_out_txt, b_cat, BCOMB);

    const dim3 blk(256);

    // 1) BOTH QKV projections in one launch (6 half segments), Q pre-scaled
    {
        GemmP p = {};
        p.A1[0] = p.A1[1] = p.A1[2] = HSh;
        p.A1[3] = p.A1[4] = p.A1[5] = TXTh;
        p.W[0] = whqi; p.W[1] = whki; p.W[2] = whvi;
        p.W[3] = whqt; p.W[4] = whkt; p.W[5] = whvt;
        p.Bi[0] = b_q_img; p.Bi[1] = b_k_img; p.Bi[2] = b_v_img;
        p.Bi[3] = b_q_txt; p.Bi[4] = b_k_txt; p.Bi[5] = b_v_txt;
        p.Ch[0] = QKV0h; p.Ch[1] = QKV0h + 512; p.Ch[2] = QKV0h + 1024;
        p.Ch[3] = QKV1h; p.Ch[4] = QKV1h + 512; p.Ch[5] = QKV1h + 1024;
        p.osc[0] = qsc; p.osc[1] = 1.f; p.osc[2] = 1.f;
        p.osc[3] = qsc; p.osc[4] = 1.f; p.osc[5] = 1.f;
        p.lda = HDIM; p.ldc = 3 * HDIM; p.K = HDIM;
        gemm_k<false><<<dim3(24, 64), blk, GSM>>>(p);
    }

    // 2) dual-KV fused attentions: one CTA = both attentions for one Q stream
    {
        FlashP p;
        // c=0 (img out): Q=q_img, KVa=img, KVb=txt -> OUTC[:, :512]
        p.Qp[0] = QKV0h; p.Kp[0] = QKV0h + 512; p.Vp[0] = QKV0h + 1024;
        p.Kp2[0] = QKV1h + 512; p.Vp2[0] = QKV1h + 1024; p.Op[0] = OUTC;
        // c=1 (txt out): Q=q_txt, KVa=txt, KVb=img -> OUTC[:, 512:]
        p.Qp[1] = QKV1h; p.Kp[1] = QKV1h + 512; p.Vp[1] = QKV1h + 1024;
        p.Kp2[1] = QKV0h + 512; p.Vp2[1] = QKV0h + 1024; p.Op[1] = OUTC + 512;
        p.sq = 3 * HDIM; p.skv = 3 * HDIM; p.so = 2 * HDIM; p.cmask = 1; p.cshift = 1;
        flash_k<true><<<dim3(SEQL / 128, 8, BATCH * 2), blk, FSM_D>>>(p);
    }

    // 3) combined out+cat gemm: OUTB = OUTC @ WCOMB^T + BCOMB (plain cp.async)
    {
        GemmP p = {};
        p.A1[0] = OUTC; p.W[0] = WCOMB; p.Bi[0] = BCOMB;
        p.Ch[0] = OUTBh; p.osc[0] = 1.f;
        p.lda = 2 * HDIM; p.ldc = HDIM; p.K = 1024;
        gemm_k<false><<<dim3(4, 64), blk, GSM>>>(p);
    }

    // 4) pooling in_proj, Q pre-scaled
    {
        GemmP p = {};
        p.A1[0] = p.A1[1] = p.A1[2] = OUTBh;
        p.W[0] = whinp; p.W[1] = whinp + 512 * 512; p.W[2] = whinp + 1024 * 512;
        p.Bi[0] = in_proj_b; p.Bi[1] = in_proj_b + 512; p.Bi[2] = in_proj_b + 1024;
        p.Ch[0] = QKV2h; p.Ch[1] = QKV2h + 512; p.Ch[2] = QKV2h + 1024;
        p.osc[0] = qsc; p.osc[1] = 1.f; p.osc[2] = 1.f;
        p.lda = HDIM; p.ldc = 3 * HDIM; p.K = HDIM;
        gemm_k<false><<<dim3(12, 64), blk, GSM>>>(p);
    }

    // 5) pooling self-attention (single-KV)
    {
        FlashP p;
        p.Qp[0] = QKV2h; p.Kp[0] = QKV2h + 512; p.Vp[0] = QKV2h + 1024;
        p.Kp2[0] = nullptr; p.Vp2[0] = nullptr; p.Op[0] = CTXh;
        p.sq = 3 * HDIM; p.skv = 3 * HDIM; p.so = HDIM; p.cmask = 0; p.cshift = 0;
        flash_k<false><<<dim3(SEQL / 128, 8, BATCH), blk, FSM_S>>>(p);
    }

    // 6) out_proj -> fp32 output
    {
        GemmP p = {};
        p.A1[0] = CTXh; p.W[0] = whop; p.Bi[0] = out_proj_b;
        p.Cf = out; p.osc[0] = 1.f;
        p.lda = HDIM; p.ldc = HDIM; p.K = HDIM;
        gemm_k<true><<<dim3(4, 64), blk, GSM>>>(p);
    }
}